// round 15
// baseline (speedup 1.0000x reference)
#include <cuda_runtime.h>
#include <cstdint>

#define IN_DIM 128
#define W_DIM 160
#define OUT_DIM 224
#define MAX_NODES 50000
#define MAXDEG 64
#define CHUNKS 4              // MAXDEG / 16
#define OVF_CAP 8192

__device__ int g_cursor[MAX_NODES];
__device__ int g_perm[MAX_NODES * MAXDEG];
__device__ int g_ovf[OVF_CAP];
__device__ int g_ovf_count;

__device__ __forceinline__ void red_add_v4(float* addr, float a, float b, float c, float d) {
    asm volatile("red.global.add.v4.f32 [%0], {%1, %2, %3, %4};"
                 :: "l"(addr), "f"(a), "f"(b), "f"(c), "f"(d)
                 : "memory");
}

// ---------- preprocessing ----------

__global__ void zero_all_kernel(float4* __restrict__ out, int n4, int n_nodes) {
    int i = blockIdx.x * blockDim.x + threadIdx.x;
    if (i < n4) out[i] = make_float4(0.f, 0.f, 0.f, 0.f);
    if (i < n_nodes) g_cursor[i] = 0;
    if (i == 0) g_ovf_count = 0;
}

__global__ void scatter_kernel(const int2* __restrict__ eidx, int n_edges) {
    int i = blockIdx.x * blockDim.x + threadIdx.x;
    if (i < n_edges) {
        int dst = __ldcs(&eidx[i]).y;
        int pos = atomicAdd(&g_cursor[dst], 1);
        if (pos < MAXDEG) {
            g_perm[dst * MAXDEG + pos] = i;
        } else {
            int oi = atomicAdd(&g_ovf_count, 1);
            if (oi < OVF_CAP) g_ovf[oi] = i;
        }
    }
}

// ---------- shared edge math: accumulate one edge's message into acc ----------

__device__ __forceinline__ void edge_accum(
    const float* __restrict__ nf, const float4* __restrict__ ang,
    const float* __restrict__ tp, int p, int src, int g, float4* acc)
{
    const float INV_SQRT3 = 0.5773502691896258f;
    const float INV_SQRT2 = 0.7071067811865476f;

    float4 y = __ldcs(&ang[p]);
    float y0 = y.x, yx = y.y, yy = y.z, yz = y.w;

    const float4* hb = (const float4*)(nf + (size_t)src * IN_DIM);
    float4 h0v  = __ldg(&hb[g]);
    float4 h1xv = __ldg(&hb[8 + g]);
    float4 h1yv = __ldg(&hb[16 + g]);
    float4 h1zv = __ldg(&hb[24 + g]);

    const float4* wb = (const float4*)(tp + (size_t)p * W_DIM);
    float4 w0v = __ldcs(&wb[g]);
    float4 w1v = __ldcs(&wb[8 + g]);
    float4 w2v = __ldcs(&wb[16 + g]);
    float4 w3v = __ldcs(&wb[24 + g]);
    float4 w4v = __ldcs(&wb[32 + g]);

    const float* h0p  = (const float*)&h0v;
    const float* h1xp = (const float*)&h1xv;
    const float* h1yp = (const float*)&h1yv;
    const float* h1zp = (const float*)&h1zv;
    const float* w0p  = (const float*)&w0v;
    const float* w1p  = (const float*)&w1v;
    const float* w2p  = (const float*)&w2v;
    const float* w3p  = (const float*)&w3v;
    const float* w4p  = (const float*)&w4v;
    float* a0 = (float*)&acc[0];
    float* a1 = (float*)&acc[1];
    float* a2 = (float*)&acc[2];
    float* a3 = (float*)&acc[3];
    float* a4 = (float*)&acc[4];
    float* a5 = (float*)&acc[5];
    float* a6 = (float*)&acc[6];

    #pragma unroll
    for (int c = 0; c < 4; c++) {
        float H0 = h0p[c], Hx = h1xp[c], Hy = h1yp[c], Hz = h1zp[c];
        float W0 = w0p[c], W1 = w1p[c], W2 = w2p[c], W3 = w3p[c], W4 = w4p[c];

        float dot = Hx * yx + Hy * yy + Hz * yz;
        a0[c] += W0 * (H0 * y0) + (W3 * INV_SQRT3) * dot;

        float a = W1 * H0;
        float b = W2 * y0;
        a1[c] += a * yx + b * Hx;
        a2[c] += a * yy + b * Hy;
        a3[c] += a * yz + b * Hz;

        float s = W4 * INV_SQRT2;
        a4[c] += s * (Hy * yz - Hz * yy);
        a5[c] += s * (Hz * yx - Hx * yz);
        a6[c] += s * (Hx * yy - Hy * yx);
    }
}

__device__ __forceinline__ void flush_acc(float* __restrict__ out, int dst, int g,
                                          const float4* acc) {
    float* ob = out + (size_t)dst * OUT_DIM + 4 * g;
    #pragma unroll
    for (int s = 0; s < 7; s++)
        red_add_v4(ob + 32 * s, acc[s].x, acc[s].y, acc[s].z, acc[s].w);
}

// ---------- main: (node, chunk) groups over fixed slots — dst known a priori ----------

__global__ __launch_bounds__(256) void conv_main_kernel(
    const float* __restrict__ nf,        // [n_nodes, 128]
    const float4* __restrict__ ang,      // [n_edges, 4]
    const int* __restrict__ eidx_raw,    // [n_edges, 2] int32, flat
    const float* __restrict__ tp,        // [n_edges, 160]
    float* __restrict__ out,             // [n_nodes, 224]
    int n_nodes)
{
    int tid = blockIdx.x * 256 + threadIdx.x;
    int grp = tid >> 3;
    int g = tid & 7;
    int node = grp >> 2;          // CHUNKS = 4
    int chunk = grp & 3;
    if (node >= n_nodes) return;

    int deg = __ldg(&g_cursor[node]);
    if (deg > MAXDEG) deg = MAXDEG;
    int cnt = deg - chunk * 16;
    if (cnt <= 0) return;
    if (cnt > 16) cnt = 16;

    // All 16 slot ids in 4 broadcast int4 loads — no serial perm chain.
    const int4* pb = (const int4*)(g_perm + node * MAXDEG + chunk * 16);
    int4 cb[4];
    cb[0] = __ldg(&pb[0]);
    cb[1] = __ldg(&pb[1]);
    cb[2] = __ldg(&pb[2]);
    cb[3] = __ldg(&pb[3]);

    float4 acc[7];
    #pragma unroll
    for (int s = 0; s < 7; s++) acc[s] = make_float4(0.f, 0.f, 0.f, 0.f);

    #pragma unroll
    for (int j = 0; j < 4; j++) {
        int pp[4] = {cb[j].x, cb[j].y, cb[j].z, cb[j].w};
        int ss[4];
        // sanitize + issue all 4 src loads first (independent)
        #pragma unroll
        for (int m = 0; m < 4; m++) {
            if (4 * j + m >= cnt) pp[m] = 0;
            ss[m] = __ldg(&eidx_raw[2 * pp[m]]);      // src
        }
        #pragma unroll
        for (int m = 0; m < 4; m++) {
            if (4 * j + m < cnt)
                edge_accum(nf, ang, tp, pp[m], ss[m], g, acc);
        }
    }

    flush_acc(out, node, g, acc);
}

// ---------- overflow cleanup (normally 0 edges) ----------

__global__ void ovf_kernel(
    const float* __restrict__ nf, const float4* __restrict__ ang,
    const int* __restrict__ eidx_raw, const float* __restrict__ tp,
    float* __restrict__ out)
{
    int total = g_ovf_count;
    if (total > OVF_CAP) total = OVF_CAP;
    int lanes = total * 8;
    for (int tid = blockIdx.x * blockDim.x + threadIdx.x; tid < lanes;
         tid += gridDim.x * blockDim.x) {
        int idx = tid >> 3;
        int g = tid & 7;
        int p = g_ovf[idx];
        int src = __ldg(&eidx_raw[2 * p]);
        int dst = __ldg(&eidx_raw[2 * p + 1]);
        float4 acc[7];
        #pragma unroll
        for (int s = 0; s < 7; s++) acc[s] = make_float4(0.f, 0.f, 0.f, 0.f);
        edge_accum(nf, ang, tp, p, src, g, acc);
        flush_acc(out, dst, g, acc);
    }
}

extern "C" void kernel_launch(void* const* d_in, const int* in_sizes, int n_in,
                              void* d_out, int out_size) {
    const float*  nf   = (const float*)d_in[0];      // node_features [n,128]
    const float4* ang  = (const float4*)d_in[1];     // edge_angular  [E,4]
    const int2*   eidx = (const int2*)d_in[2];       // edge_index    [E,2] int32
    const float*  tp   = (const float*)d_in[3];      // tp_weights    [E,160]
    float*        out  = (float*)d_out;

    int n_edges = in_sizes[1] / 4;
    int n_nodes = in_sizes[0] / IN_DIM;
    int n4 = out_size / 4;

    zero_all_kernel<<<(n4 + 255) / 256, 256>>>((float4*)d_out, n4, n_nodes);
    scatter_kernel<<<(n_edges + 255) / 256, 256>>>(eidx, n_edges);

    int groups = n_nodes * CHUNKS;
    int total_threads = groups * 8;
    int blocks = (total_threads + 255) / 256;
    conv_main_kernel<<<blocks, 256>>>(nf, ang, (const int*)eidx, tp, out, n_nodes);

    ovf_kernel<<<16, 256>>>(nf, ang, (const int*)eidx, tp, out);
}

// round 16
// speedup vs baseline: 1.5001x; 1.5001x over previous
#include <cuda_runtime.h>
#include <cstdint>

#define IN_DIM 128
#define W_DIM 160
#define OUT_DIM 224
#define MAX_NODES 50000
#define MAXDEG 64
#define CHUNKS 4              // MAXDEG / 16
#define OVF_CAP 8192

__device__ int g_cursor[MAX_NODES];
__device__ int g_perm[MAX_NODES * MAXDEG];
__device__ int g_ovf[OVF_CAP];
__device__ int g_ovf_count;

__device__ __forceinline__ void red_add_v4(float* addr, float a, float b, float c, float d) {
    asm volatile("red.global.add.v4.f32 [%0], {%1, %2, %3, %4};"
                 :: "l"(addr), "f"(a), "f"(b), "f"(c), "f"(d)
                 : "memory");
}

// ---------- preprocessing ----------

__global__ void zero_all_kernel(float4* __restrict__ out, int n4, int n_nodes) {
    int i = blockIdx.x * blockDim.x + threadIdx.x;
    if (i < n4) out[i] = make_float4(0.f, 0.f, 0.f, 0.f);
    if (i < n_nodes) g_cursor[i] = 0;
    if (i == 0) g_ovf_count = 0;
}

__global__ void scatter_kernel(const int2* __restrict__ eidx, int n_edges) {
    int i = blockIdx.x * blockDim.x + threadIdx.x;
    if (i < n_edges) {
        int dst = __ldcs(&eidx[i]).y;
        int pos = atomicAdd(&g_cursor[dst], 1);
        if (pos < MAXDEG) {
            g_perm[dst * MAXDEG + pos] = i;
        } else {
            int oi = atomicAdd(&g_ovf_count, 1);
            if (oi < OVF_CAP) g_ovf[oi] = i;
        }
    }
}

// ---------- shared edge math: accumulate one edge's message into acc ----------

__device__ __forceinline__ void edge_accum(
    const float* __restrict__ nf, const float4* __restrict__ ang,
    const float* __restrict__ tp, int p, int src, int g, float4* acc)
{
    const float INV_SQRT3 = 0.5773502691896258f;
    const float INV_SQRT2 = 0.7071067811865476f;

    float4 y = __ldcs(&ang[p]);
    float y0 = y.x, yx = y.y, yy = y.z, yz = y.w;

    const float4* hb = (const float4*)(nf + (size_t)src * IN_DIM);
    float4 h0v  = __ldg(&hb[g]);
    float4 h1xv = __ldg(&hb[8 + g]);
    float4 h1yv = __ldg(&hb[16 + g]);
    float4 h1zv = __ldg(&hb[24 + g]);

    const float4* wb = (const float4*)(tp + (size_t)p * W_DIM);
    float4 w0v = __ldcs(&wb[g]);
    float4 w1v = __ldcs(&wb[8 + g]);
    float4 w2v = __ldcs(&wb[16 + g]);
    float4 w3v = __ldcs(&wb[24 + g]);
    float4 w4v = __ldcs(&wb[32 + g]);

    const float* h0p  = (const float*)&h0v;
    const float* h1xp = (const float*)&h1xv;
    const float* h1yp = (const float*)&h1yv;
    const float* h1zp = (const float*)&h1zv;
    const float* w0p  = (const float*)&w0v;
    const float* w1p  = (const float*)&w1v;
    const float* w2p  = (const float*)&w2v;
    const float* w3p  = (const float*)&w3v;
    const float* w4p  = (const float*)&w4v;
    float* a0 = (float*)&acc[0];
    float* a1 = (float*)&acc[1];
    float* a2 = (float*)&acc[2];
    float* a3 = (float*)&acc[3];
    float* a4 = (float*)&acc[4];
    float* a5 = (float*)&acc[5];
    float* a6 = (float*)&acc[6];

    #pragma unroll
    for (int c = 0; c < 4; c++) {
        float H0 = h0p[c], Hx = h1xp[c], Hy = h1yp[c], Hz = h1zp[c];
        float W0 = w0p[c], W1 = w1p[c], W2 = w2p[c], W3 = w3p[c], W4 = w4p[c];

        float dot = Hx * yx + Hy * yy + Hz * yz;
        a0[c] += W0 * (H0 * y0) + (W3 * INV_SQRT3) * dot;

        float a = W1 * H0;
        float b = W2 * y0;
        a1[c] += a * yx + b * Hx;
        a2[c] += a * yy + b * Hy;
        a3[c] += a * yz + b * Hz;

        float s = W4 * INV_SQRT2;
        a4[c] += s * (Hy * yz - Hz * yy);
        a5[c] += s * (Hz * yx - Hx * yz);
        a6[c] += s * (Hx * yy - Hy * yx);
    }
}

__device__ __forceinline__ void flush_acc(float* __restrict__ out, int dst, int g,
                                          const float4* acc) {
    float* ob = out + (size_t)dst * OUT_DIM + 4 * g;
    #pragma unroll
    for (int s = 0; s < 7; s++)
        red_add_v4(ob + 32 * s, acc[s].x, acc[s].y, acc[s].z, acc[s].w);
}

// ---------- main: chunk-major mapping — each warp = same chunk of 4 nodes ----------
// gridDim.y = chunk index. Chunk-0 warps are uniformly full (~deg 16);
// chunk>=1 warps exit after one deg load. All 32 lanes active in hot warps.

__global__ __launch_bounds__(256) void conv_main_kernel(
    const float* __restrict__ nf,        // [n_nodes, 128]
    const float4* __restrict__ ang,      // [n_edges, 4]
    const int* __restrict__ eidx_raw,    // [n_edges, 2] int32, flat
    const float* __restrict__ tp,        // [n_edges, 160]
    float* __restrict__ out,             // [n_nodes, 224]
    int n_nodes)
{
    int t = blockIdx.x * 256 + threadIdx.x;
    int node = t >> 3;
    int g = t & 7;
    int chunk = blockIdx.y;
    if (node >= n_nodes) return;

    int deg = __ldg(&g_cursor[node]);
    if (deg > MAXDEG) deg = MAXDEG;
    int cnt = deg - chunk * 16;
    if (cnt <= 0) return;
    if (cnt > 16) cnt = 16;

    // All 16 slot ids in 4 broadcast int4 loads — no serial perm chain.
    const int4* pb = (const int4*)(g_perm + node * MAXDEG + chunk * 16);
    int4 cb[4];
    cb[0] = __ldg(&pb[0]);
    cb[1] = __ldg(&pb[1]);
    cb[2] = __ldg(&pb[2]);
    cb[3] = __ldg(&pb[3]);

    float4 acc[7];
    #pragma unroll
    for (int s = 0; s < 7; s++) acc[s] = make_float4(0.f, 0.f, 0.f, 0.f);

    #pragma unroll
    for (int j = 0; j < 4; j++) {
        int pp[4] = {cb[j].x, cb[j].y, cb[j].z, cb[j].w};
        int ss[4];
        // sanitize + issue all 4 src loads first (independent)
        #pragma unroll
        for (int m = 0; m < 4; m++) {
            if (4 * j + m >= cnt) pp[m] = 0;
            ss[m] = __ldg(&eidx_raw[2 * pp[m]]);      // src
        }
        #pragma unroll
        for (int m = 0; m < 4; m++) {
            if (4 * j + m < cnt)
                edge_accum(nf, ang, tp, pp[m], ss[m], g, acc);
        }
    }

    flush_acc(out, node, g, acc);
}

// ---------- overflow cleanup (normally 0 edges) ----------

__global__ void ovf_kernel(
    const float* __restrict__ nf, const float4* __restrict__ ang,
    const int* __restrict__ eidx_raw, const float* __restrict__ tp,
    float* __restrict__ out)
{
    int total = g_ovf_count;
    if (total > OVF_CAP) total = OVF_CAP;
    int lanes = total * 8;
    for (int tid = blockIdx.x * blockDim.x + threadIdx.x; tid < lanes;
         tid += gridDim.x * blockDim.x) {
        int idx = tid >> 3;
        int g = tid & 7;
        int p = g_ovf[idx];
        int src = __ldg(&eidx_raw[2 * p]);
        int dst = __ldg(&eidx_raw[2 * p + 1]);
        float4 acc[7];
        #pragma unroll
        for (int s = 0; s < 7; s++) acc[s] = make_float4(0.f, 0.f, 0.f, 0.f);
        edge_accum(nf, ang, tp, p, src, g, acc);
        flush_acc(out, dst, g, acc);
    }
}

extern "C" void kernel_launch(void* const* d_in, const int* in_sizes, int n_in,
                              void* d_out, int out_size) {
    const float*  nf   = (const float*)d_in[0];      // node_features [n,128]
    const float4* ang  = (const float4*)d_in[1];     // edge_angular  [E,4]
    const int2*   eidx = (const int2*)d_in[2];       // edge_index    [E,2] int32
    const float*  tp   = (const float*)d_in[3];      // tp_weights    [E,160]
    float*        out  = (float*)d_out;

    int n_edges = in_sizes[1] / 4;
    int n_nodes = in_sizes[0] / IN_DIM;
    int n4 = out_size / 4;

    zero_all_kernel<<<(n4 + 255) / 256, 256>>>((float4*)d_out, n4, n_nodes);
    scatter_kernel<<<(n_edges + 255) / 256, 256>>>(eidx, n_edges);

    dim3 grid((n_nodes * 8 + 255) / 256, CHUNKS);
    conv_main_kernel<<<grid, 256>>>(nf, ang, (const int*)eidx, tp, out, n_nodes);

    ovf_kernel<<<8, 256>>>(nf, ang, (const int*)eidx, tp, out);
}